// round 4
// baseline (speedup 1.0000x reference)
#include <cuda_runtime.h>
#include <cstddef>

#define BATCH 32
#define DCH 256
#define NG 64
#define PPAD 1088   // padded total conv positions (17 * 64)

__constant__ int c_off[31] = {0,64,128,192,252,312,372,432,488,544,600,656,708,760,812,
                              864,888,912,936,960,980,1000,1020,
                              1040,1048,1056,1064,1072,1076,1080,1084};
static const int h_off[31] = {0,64,128,192,252,312,372,432,488,544,600,656,708,760,812,
                              864,888,912,936,960,980,1000,1020,
                              1040,1048,1056,1064,1072,1076,1080,1084};

// ---------------- scratch ----------------
__device__ float g_wT2[29 * 512 * 256];
__device__ float g_wT3[2 * 768 * 256];
__device__ float g_wP[256 * 768];
__device__ float g_cur[(size_t)BATCH * DCH * PPAD];
__device__ float g_Pc[(size_t)BATCH * PPAD * DCH];
__device__ float g_P[(size_t)BATCH * NG * 768];

// ---------------- f32x2 helper ----------------
__device__ __forceinline__ void fma2(unsigned long long& d, unsigned long long a,
                                     unsigned long long b) {
    asm("fma.rn.f32x2 %0, %1, %2, %3;" : "=l"(d) : "l"(a), "l"(b), "l"(d));
}

// ---------------- generalized transpose ----------------
__global__ void trans_k(const float* __restrict__ in, float* __restrict__ out,
                        int R, int C, int in_ld, int out_ld,
                        size_t in_bs, size_t out_bs) {
    __shared__ float tile[32][33];
    int bat = blockIdx.z;
    int c0 = blockIdx.x * 32, r0 = blockIdx.y * 32;
    const float* ib = in + (size_t)bat * in_bs;
    float* ob = out + (size_t)bat * out_bs;
    int tx = threadIdx.x, ty = threadIdx.y;
#pragma unroll
    for (int s = 0; s < 32; s += 8) {
        int r = r0 + ty + s, c = c0 + tx;
        if (r < R && c < C) tile[ty + s][tx] = ib[(size_t)r * in_ld + c];
    }
    __syncthreads();
#pragma unroll
    for (int s = 0; s < 32; s += 8) {
        int c = c0 + ty + s, r = r0 + tx;
        if (c < C && r < R) ob[(size_t)c * out_ld + r] = tile[tx][ty + s];
    }
}

// ---------------- conv-as-GEMM: 512 threads, 4 warpgroups split K ----------------
// out[b, n, m] (!TRANS) or out[b, m, n] (TRANS)
//   = bias[n] + sum_{c,kk} in[b, c, in_off + m*cstride + kk] * wT[(c*KSZ+kk)*wld + n]
// A stored in SMEM pre-duplicated (float2{v,v}) for direct fma.rn.f32x2 operands.
template <int KSZ, int TM, bool TRANS>
__global__ void __launch_bounds__(512, 1) conv_gemm4(
    const float* __restrict__ in, int in_row_len, int in_off, int cstride,
    const float* __restrict__ wT, int wld,
    const float* __restrict__ bias,
    float* __restrict__ out, int out_ld, int out_off, int M_total) {
    constexpr int KTOT = KSZ * 256;
    constexpr int KQ = KTOT / 4;                 // per-warpgroup K
    constexpr int KC = (KSZ == 3) ? 24 : 16;     // K chunk
    constexpr int NCH = KQ / KC;
    constexpr int AG = 128 / TM;                 // A-load row groups
    constexpr int NA = KC / AG;
    constexpr int NB = KC / 8;
    constexpr int MR = TM / 16;                  // per-thread M rows
    constexpr int TM2 = TM * 2;                  // duplicated A row floats
    constexpr int WGS = 2 * KC * TM2 + 2 * KC * 64;  // floats per warpgroup block

    extern __shared__ float smem[];
    int tid = threadIdx.x;
    int wg = tid >> 7;          // 0..3
    int wtid = tid & 127;
    float* As = smem + wg * WGS;           // duplicated: [2][KC][TM2]
    float* Bs = As + 2 * KC * TM2;         // [2][KC][64]

    int b = blockIdx.z;
    int nblk = blockIdx.y * 64;
    int mblk = blockIdx.x * TM;
    int m0 = (wtid & 15) * MR;
    int n0 = (wtid >> 4) * 8;

    int am = wtid % TM;
    int ak0 = wtid / TM;
    int bkb = wtid >> 4;
    int bn = (wtid & 15) * 4;

    const float* inb = in + (size_t)b * DCH * in_row_len + in_off;
    int kbase = wg * KQ;

    float aA[NA];
    float4 bB[NB];
    auto gload = [&](int ch) {
        int c0k = kbase + ch * KC;
#pragma unroll
        for (int i = 0; i < NA; i++) {
            int k = c0k + ak0 + AG * i;
            int c = k / KSZ;
            int kk = k - c * KSZ;
            int mm = mblk + am;
            aA[i] = (mm < M_total)
                        ? inb[(size_t)c * in_row_len + mm * cstride + kk]
                        : 0.f;
        }
#pragma unroll
        for (int i = 0; i < NB; i++) {
            int k = c0k + bkb + 8 * i;
            bB[i] = *(const float4*)&wT[(size_t)k * wld + nblk + bn];
        }
    };
    auto sts = [&](int buf) {
#pragma unroll
        for (int i = 0; i < NA; i++) {
            float2 d;
            d.x = aA[i];
            d.y = aA[i];
            *(float2*)&As[buf * KC * TM2 + (ak0 + AG * i) * TM2 + am * 2] = d;
        }
#pragma unroll
        for (int i = 0; i < NB; i++)
            *(float4*)&Bs[buf * KC * 64 + (bkb + 8 * i) * 64 + bn] = bB[i];
    };

    unsigned long long acc[MR][4];
#pragma unroll
    for (int mi = 0; mi < MR; mi++)
#pragma unroll
        for (int p = 0; p < 4; p++) acc[mi][p] = 0ULL;

    gload(0);
    sts(0);
    __syncthreads();

    for (int ch = 0; ch < NCH; ch++) {
        int buf = ch & 1;
        if (ch + 1 < NCH) gload(ch + 1);
#pragma unroll
        for (int k = 0; k < KC; k++) {
            unsigned long long a[MR];
            const float* ap = &As[buf * KC * TM2 + k * TM2 + m0 * 2];
            if (MR == 4) {
                ulonglong2 a01 = *(const ulonglong2*)ap;
                ulonglong2 a23 = *(const ulonglong2*)(ap + 4);
                a[0] = a01.x; a[1] = a01.y; a[2] = a23.x; a[3] = a23.y;
            } else if (MR == 2) {
                ulonglong2 a01 = *(const ulonglong2*)ap;
                a[0] = a01.x; a[1] = a01.y;
            } else {
                a[0] = *(const unsigned long long*)ap;
            }
            const float* bp = &Bs[buf * KC * 64 + k * 64 + n0];
            ulonglong2 bl = *(const ulonglong2*)bp;
            ulonglong2 bh = *(const ulonglong2*)(bp + 4);
#pragma unroll
            for (int mi = 0; mi < MR; mi++) {
                fma2(acc[mi][0], a[mi], bl.x);
                fma2(acc[mi][1], a[mi], bl.y);
                fma2(acc[mi][2], a[mi], bh.x);
                fma2(acc[mi][3], a[mi], bh.y);
            }
        }
        if (ch + 1 < NCH) {
            sts(buf ^ 1);
            __syncthreads();
        }
    }

    float res[MR][8];
#pragma unroll
    for (int mi = 0; mi < MR; mi++)
#pragma unroll
        for (int p = 0; p < 4; p++) {
            union { unsigned long long u; float2 f; } cv;
            cv.u = acc[mi][p];
            res[mi][2 * p] = cv.f.x;
            res[mi][2 * p + 1] = cv.f.y;
        }

    // ---- 4-way reduction: wgs 1..3 dump to smem (aliased), wg0 sums ----
    __syncthreads();
    float* Red = smem;  // [3][TM][64]
    if (wg != 0) {
        float* rbase = Red + (wg - 1) * TM * 64;
#pragma unroll
        for (int mi = 0; mi < MR; mi++) {
            float* rp = &rbase[(m0 + mi) * 64 + n0];
            *(float4*)rp = make_float4(res[mi][0], res[mi][1], res[mi][2], res[mi][3]);
            *(float4*)(rp + 4) =
                make_float4(res[mi][4], res[mi][5], res[mi][6], res[mi][7]);
        }
    }
    __syncthreads();
    if (wg != 0) return;

#pragma unroll
    for (int w = 0; w < 3; w++) {
        const float* rbase = Red + w * TM * 64;
#pragma unroll
        for (int mi = 0; mi < MR; mi++) {
            const float* rp = &rbase[(m0 + mi) * 64 + n0];
#pragma unroll
            for (int j = 0; j < 8; j++) res[mi][j] += rp[j];
        }
    }

    if (!TRANS) {
#pragma unroll
        for (int j = 0; j < 8; j++) {
            int n = nblk + n0 + j;
            float bv = bias ? __ldg(bias + n) : 0.f;
            float* orow = out + ((size_t)b * DCH + n) * out_ld + out_off + mblk + m0;
            if (mblk + m0 + MR <= M_total) {
                if (MR == 4) {
                    *(float4*)orow = make_float4(res[0][j] + bv, res[1][j] + bv,
                                                 res[2][j] + bv, res[3][j] + bv);
                } else if (MR == 2) {
                    *(float2*)orow = make_float2(res[0][j] + bv, res[1][j] + bv);
                } else {
                    orow[0] = res[0][j] + bv;
                }
            } else {
#pragma unroll
                for (int mi = 0; mi < MR; mi++)
                    if (mblk + m0 + mi < M_total) orow[mi] = res[mi][j] + bv;
            }
        }
    } else {
#pragma unroll
        for (int mi = 0; mi < MR; mi++) {
            int mm = mblk + m0 + mi;
            if (mm < M_total) {
                float* op = out + ((size_t)b * M_total + mm) * out_ld + nblk + n0;
                *(float4*)op = make_float4(res[mi][0], res[mi][1], res[mi][2], res[mi][3]);
                *(float4*)(op + 4) =
                    make_float4(res[mi][4], res[mi][5], res[mi][6], res[mi][7]);
            }
        }
    }
}

// ---------------- final output assembly ----------------
__global__ void __launch_bounds__(256) final_out(
    const float* __restrict__ P, const float* __restrict__ Pc,
    const float* __restrict__ vis_b, float* __restrict__ out) {
    int i = blockIdx.x;
    int b = blockIdx.y;
    int o = threadIdx.x;

    __shared__ int lut[64];
    if (o < 64) {
        int j = o;
        int d = j - i;
        int pg = -1;
        if (d >= 1 && d <= 15) {
            pg = c_off[d - 1] + i;
        } else if (d >= 17 && d <= 31 && ((d - 17) & 1) == 0 && (i & 1) == 0) {
            pg = c_off[15 + ((d - 17) >> 1)] + (i >> 1);
        } else if (d >= 35 && d <= 63 && ((d - 35) & 3) == 0 && (i & 3) == 0) {
            pg = c_off[23 + ((d - 35) >> 2)] + (i >> 2);
        }
        lut[j] = pg;
    }
    __syncthreads();

    float vb = __ldg(vis_b + o);
    float p1 = P[((size_t)b * NG + i) * 768 + o];
    float p2x = P[((size_t)b * NG + i) * 768 + 256 + o];
    const float* P3b = P + (size_t)b * NG * 768 + 512 + o;
    const float* Pcb = Pc + (size_t)b * PPAD * 256 + o;

    float accr[64];
#pragma unroll
    for (int j = 0; j < 64; j++) {
        float v = vb;
        if (j == i) {
            v += p1 + p2x + P3b[(size_t)j * 768];
        } else {
            int pg = lut[j];
            if (pg >= 0) v += p1 + Pcb[(size_t)pg * 256] + P3b[(size_t)j * 768];
        }
        accr[j] = v;
    }

    float4* op = (float4*)(out + (((size_t)b * DCH + o) * NG + i) * NG);
#pragma unroll
    for (int q = 0; q < 16; q++)
        op[q] = make_float4(accr[4 * q], accr[4 * q + 1], accr[4 * q + 2], accr[4 * q + 3]);
}

// ---------------- host ----------------
static inline int smem_bytes4(int ksz, int tm) {
    int kc = (ksz == 3) ? 24 : 16;
    int wgs = 2 * kc * (tm * 2) + 2 * kc * 64;  // floats per wg
    int total = 4 * wgs * 4;                    // bytes
    int red = 3 * tm * 64 * 4;
    return total > red ? total : red;
}

extern "C" void kernel_launch(void* const* d_in, const int* in_sizes, int n_in,
                              void* d_out, int out_size) {
    const float* x  = (const float*)d_in[0];
    const float* w2 = (const float*)d_in[1];
    const float* b2 = (const float*)d_in[2];
    const float* w3 = (const float*)d_in[3];
    const float* b3 = (const float*)d_in[4];
    const float* vw = (const float*)d_in[5];
    const float* vb = (const float*)d_in[6];
    float* out = (float*)d_out;

    float *wT2, *wT3, *wP, *cur, *Pc, *P;
    cudaGetSymbolAddress((void**)&wT2, g_wT2);
    cudaGetSymbolAddress((void**)&wT3, g_wT3);
    cudaGetSymbolAddress((void**)&wP, g_wP);
    cudaGetSymbolAddress((void**)&cur, g_cur);
    cudaGetSymbolAddress((void**)&Pc, g_Pc);
    cudaGetSymbolAddress((void**)&P, g_P);

    cudaFuncSetAttribute(conv_gemm4<2, 64, false>,
                         cudaFuncAttributeMaxDynamicSharedMemorySize, smem_bytes4(2, 64));
    cudaFuncSetAttribute(conv_gemm4<2, 32, false>,
                         cudaFuncAttributeMaxDynamicSharedMemorySize, smem_bytes4(2, 32));
    cudaFuncSetAttribute(conv_gemm4<2, 16, false>,
                         cudaFuncAttributeMaxDynamicSharedMemorySize, smem_bytes4(2, 16));
    cudaFuncSetAttribute(conv_gemm4<3, 32, false>,
                         cudaFuncAttributeMaxDynamicSharedMemorySize, smem_bytes4(3, 32));
    cudaFuncSetAttribute(conv_gemm4<3, 16, false>,
                         cudaFuncAttributeMaxDynamicSharedMemorySize, smem_bytes4(3, 16));
    cudaFuncSetAttribute(conv_gemm4<1, 64, true>,
                         cudaFuncAttributeMaxDynamicSharedMemorySize, smem_bytes4(1, 64));

    dim3 tb(32, 8);
    trans_k<<<dim3(512 / 32, 256 / 32, 29), tb>>>(w2, wT2, 256, 512, 512, 256,
                                                  (size_t)256 * 512, (size_t)256 * 512);
    trans_k<<<dim3(768 / 32, 256 / 32, 2), tb>>>(w3, wT3, 256, 768, 768, 256,
                                                 (size_t)256 * 768, (size_t)256 * 768);
    trans_k<<<dim3(256 / 32, 256 / 32, 3), tb>>>(vw, wP, 256, 256, 768, 768,
                                                 (size_t)256, (size_t)256);

    int i2 = 0, i3 = 0;
    int Lprev = NG;
    for (int l = 0; l < 31; l++) {
        int ksz = (l == 15 || l == 23) ? 3 : 2;
        int cs = (ksz == 3) ? 2 : 1;
        int Lout = (Lprev - ksz) / cs + 1;
        const float* inp = (l == 0) ? x : cur;
        int in_row = (l == 0) ? NG : PPAD;
        int in_off = (l == 0) ? 0 : h_off[l - 1];
        dim3 grid(1, 4, BATCH);
        if (ksz == 2) {
            const float* wt = wT2 + (size_t)i2 * 512 * 256;
            const float* bi = b2 + (size_t)i2 * 256;
            i2++;
            if (Lout > 32)
                conv_gemm4<2, 64, false><<<grid, 512, smem_bytes4(2, 64)>>>(
                    inp, in_row, in_off, cs, wt, 256, bi, cur, PPAD, h_off[l], Lout);
            else if (Lout > 16)
                conv_gemm4<2, 32, false><<<grid, 512, smem_bytes4(2, 32)>>>(
                    inp, in_row, in_off, cs, wt, 256, bi, cur, PPAD, h_off[l], Lout);
            else
                conv_gemm4<2, 16, false><<<grid, 512, smem_bytes4(2, 16)>>>(
                    inp, in_row, in_off, cs, wt, 256, bi, cur, PPAD, h_off[l], Lout);
        } else {
            const float* wt = wT3 + (size_t)i3 * 768 * 256;
            const float* bi = b3 + (size_t)i3 * 256;
            i3++;
            if (Lout > 16)
                conv_gemm4<3, 32, false><<<grid, 512, smem_bytes4(3, 32)>>>(
                    inp, in_row, in_off, cs, wt, 256, bi, cur, PPAD, h_off[l], Lout);
            else
                conv_gemm4<3, 16, false><<<grid, 512, smem_bytes4(3, 16)>>>(
                    inp, in_row, in_off, cs, wt, 256, bi, cur, PPAD, h_off[l], Lout);
        }
        Lprev = Lout;
    }

    // merged x projections: [B][64][768]
    conv_gemm4<1, 64, true><<<dim3(1, 12, BATCH), 512, smem_bytes4(1, 64)>>>(
        x, NG, 0, 1, wP, 768, nullptr, P, 768, 0, NG);
    // Pc: [B][1088][256]
    conv_gemm4<1, 64, true><<<dim3(17, 4, BATCH), 512, smem_bytes4(1, 64)>>>(
        cur, PPAD, 0, 1, wP + 256, 768, nullptr, Pc, 256, 0, PPAD);

    final_out<<<dim3(NG, BATCH), 256>>>(P, Pc, vb, out);
}

// round 5
// speedup vs baseline: 1.3354x; 1.3354x over previous
#include <cuda_runtime.h>
#include <cstddef>

#define BATCH 32
#define DCH 256
#define NG 64
#define PPAD 1088   // padded total conv positions (17 * 64)

__constant__ int c_off[31] = {0,64,128,192,252,312,372,432,488,544,600,656,708,760,812,
                              864,888,912,936,960,980,1000,1020,
                              1040,1048,1056,1064,1072,1076,1080,1084};
static const int h_off[31] = {0,64,128,192,252,312,372,432,488,544,600,656,708,760,812,
                              864,888,912,936,960,980,1000,1020,
                              1040,1048,1056,1064,1072,1076,1080,1084};

// ---------------- scratch ----------------
__device__ float g_wT2[29 * 512 * 256];
__device__ float g_wT3[2 * 768 * 256];
__device__ float g_wP[256 * 768];
__device__ float g_cur[(size_t)BATCH * DCH * PPAD];
__device__ float g_Pc[(size_t)BATCH * PPAD * DCH];
__device__ float g_P[(size_t)BATCH * NG * 768];

// ---------------- f32x2 helpers ----------------
__device__ __forceinline__ void fma2(unsigned long long& d, unsigned long long a,
                                     unsigned long long b) {
    asm("fma.rn.f32x2 %0, %1, %2, %3;" : "=l"(d) : "l"(a), "l"(b), "l"(d));
}
__device__ __forceinline__ unsigned long long dup2(float x) {
    unsigned long long r;
    unsigned int xi = __float_as_uint(x);
    asm("mov.b64 %0, {%1, %1};" : "=l"(r) : "r"(xi));
    return r;
}

// ---------------- generalized transpose ----------------
__global__ void trans_k(const float* __restrict__ in, float* __restrict__ out,
                        int R, int C, int in_ld, int out_ld,
                        size_t in_bs, size_t out_bs) {
    __shared__ float tile[32][33];
    int bat = blockIdx.z;
    int c0 = blockIdx.x * 32, r0 = blockIdx.y * 32;
    const float* ib = in + (size_t)bat * in_bs;
    float* ob = out + (size_t)bat * out_bs;
    int tx = threadIdx.x, ty = threadIdx.y;
#pragma unroll
    for (int s = 0; s < 32; s += 8) {
        int r = r0 + ty + s, c = c0 + tx;
        if (r < R && c < C) tile[ty + s][tx] = ib[(size_t)r * in_ld + c];
    }
    __syncthreads();
#pragma unroll
    for (int s = 0; s < 32; s += 8) {
        int c = c0 + ty + s, r = r0 + tx;
        if (c < C && r < R) ob[(size_t)c * out_ld + r] = tile[tx][ty + s];
    }
}

// ---------------- conv-as-GEMM: 256 threads = 4 K-slices x 64 threads ----------------
// out[b, n, m] (!TRANS) or out[b, m, n] (TRANS)
//   = bias[n] + sum_{c,kk} in[b, c, in_off + m*cstride + kk] * wT[(c*KSZ+kk)*wld + n]
// Per-thread fragment: MR(M) x 8(N), MR = TM/8. 64 threads cover 64x64 tile per slice.
template <int KSZ, int TM, bool TRANS>
__global__ void __launch_bounds__(256) conv_gemmX(
    const float* __restrict__ in, int in_row_len, int in_off, int cstride,
    const float* __restrict__ wT, int wld,
    const float* __restrict__ bias,
    float* __restrict__ out, int out_ld, int out_off, int M_total) {
    constexpr int KTOT = KSZ * 256;
    constexpr int KQ = KTOT / 4;       // per-slice K
    constexpr int KC = 16;             // K chunk
    constexpr int NCH = KQ / KC;
    constexpr int AG = 64 / TM;        // A-load row stride groups
    constexpr int NA = KC / AG;
    constexpr int NB = KC / 4;         // B float4 loads per thread
    constexpr int MR = TM / 8;         // per-thread M rows (8 / 4 / 2)
    constexpr int WGS = 2 * KC * TM + 2 * KC * 64;

    extern __shared__ float smem[];
    int tid = threadIdx.x;
    int sg = tid >> 6;         // K-slice 0..3
    int s_tid = tid & 63;
    float* As = smem + sg * WGS;          // [2][KC][TM]
    float* Bs = As + 2 * KC * TM;         // [2][KC][64]

    int b = blockIdx.z;
    int nblk = blockIdx.y * 64;
    int mblk = blockIdx.x * TM;
    int mg = s_tid & 7;
    int ng = s_tid >> 3;
    int m0 = mg * MR;
    int n0 = ng * 8;

    int am = s_tid % TM;
    int ak0 = s_tid / TM;
    int bkb = s_tid >> 4;          // 0..3
    int bn = (s_tid & 15) * 4;

    const float* inb = in + (size_t)b * DCH * in_row_len + in_off;
    int kbase = sg * KQ;

    float aA[NA];
    float4 bB[NB];
    auto gload = [&](int ch) {
        int c0k = kbase + ch * KC;
#pragma unroll
        for (int i = 0; i < NA; i++) {
            int k = c0k + ak0 + AG * i;
            int c = k / KSZ;
            int kk = k - c * KSZ;
            int mm = mblk + am;
            aA[i] = (mm < M_total)
                        ? inb[(size_t)c * in_row_len + mm * cstride + kk]
                        : 0.f;
        }
#pragma unroll
        for (int i = 0; i < NB; i++) {
            int k = c0k + bkb + 4 * i;
            bB[i] = *(const float4*)&wT[(size_t)k * wld + nblk + bn];
        }
    };
    auto sts = [&](int buf) {
#pragma unroll
        for (int i = 0; i < NA; i++)
            As[buf * KC * TM + (ak0 + AG * i) * TM + am] = aA[i];
#pragma unroll
        for (int i = 0; i < NB; i++)
            *(float4*)&Bs[buf * KC * 64 + (bkb + 4 * i) * 64 + bn] = bB[i];
    };

    unsigned long long acc[MR][4];
#pragma unroll
    for (int mi = 0; mi < MR; mi++)
#pragma unroll
        for (int p = 0; p < 4; p++) acc[mi][p] = 0ULL;

    gload(0);
    sts(0);
    __syncthreads();

    for (int ch = 0; ch < NCH; ch++) {
        int buf = ch & 1;
        if (ch + 1 < NCH) gload(ch + 1);
#pragma unroll
        for (int k = 0; k < KC; k++) {
            float a[MR];
            const float* ap = &As[buf * KC * TM + k * TM + m0];
            if (MR == 8) {
                float4 v0 = *(const float4*)ap;
                float4 v1 = *(const float4*)(ap + 4);
                a[0] = v0.x; a[1] = v0.y; a[2] = v0.z; a[3] = v0.w;
                a[4] = v1.x; a[5] = v1.y; a[6] = v1.z; a[7] = v1.w;
            } else if (MR == 4) {
                float4 v = *(const float4*)ap;
                a[0] = v.x; a[1] = v.y; a[2] = v.z; a[3] = v.w;
            } else {
                float2 v = *(const float2*)ap;
                a[0] = v.x; a[1] = v.y;
            }
            const float* bp = &Bs[buf * KC * 64 + k * 64 + n0];
            ulonglong2 bl = *(const ulonglong2*)bp;
            ulonglong2 bh = *(const ulonglong2*)(bp + 4);
#pragma unroll
            for (int mi = 0; mi < MR; mi++) {
                unsigned long long ad = dup2(a[mi]);
                fma2(acc[mi][0], ad, bl.x);
                fma2(acc[mi][1], ad, bl.y);
                fma2(acc[mi][2], ad, bh.x);
                fma2(acc[mi][3], ad, bh.y);
            }
        }
        if (ch + 1 < NCH) {
            sts(buf ^ 1);
            __syncthreads();
        }
    }

    float res[MR][8];
#pragma unroll
    for (int mi = 0; mi < MR; mi++)
#pragma unroll
        for (int p = 0; p < 4; p++) {
            union { unsigned long long u; float2 f; } cv;
            cv.u = acc[mi][p];
            res[mi][2 * p] = cv.f.x;
            res[mi][2 * p + 1] = cv.f.y;
        }

    // ---- 4-way reduction: slices 1..3 dump to smem (aliased), slice 0 sums ----
    __syncthreads();
    float* Red = smem;  // [3][TM][64]
    if (sg != 0) {
        float* rbase = Red + (sg - 1) * TM * 64;
#pragma unroll
        for (int mi = 0; mi < MR; mi++) {
            float* rp = &rbase[(m0 + mi) * 64 + n0];
            *(float4*)rp = make_float4(res[mi][0], res[mi][1], res[mi][2], res[mi][3]);
            *(float4*)(rp + 4) =
                make_float4(res[mi][4], res[mi][5], res[mi][6], res[mi][7]);
        }
    }
    __syncthreads();
    if (sg != 0) return;

#pragma unroll
    for (int w = 0; w < 3; w++) {
        const float* rbase = Red + w * TM * 64;
#pragma unroll
        for (int mi = 0; mi < MR; mi++) {
            const float* rp = &rbase[(m0 + mi) * 64 + n0];
#pragma unroll
            for (int j = 0; j < 8; j++) res[mi][j] += rp[j];
        }
    }

    if (!TRANS) {
#pragma unroll
        for (int j = 0; j < 8; j++) {
            int n = nblk + n0 + j;
            float bv = bias ? __ldg(bias + n) : 0.f;
            float* orow = out + ((size_t)b * DCH + n) * out_ld + out_off + mblk + m0;
            if (mblk + m0 + MR <= M_total) {
#pragma unroll
                for (int q = 0; q < MR; q += 4) {
                    if (MR >= 4) {
                        *(float4*)(orow + q) =
                            make_float4(res[q][j] + bv, res[q + 1][j] + bv,
                                        res[q + 2][j] + bv, res[q + 3][j] + bv);
                    } else {
                        *(float2*)(orow + q) =
                            make_float2(res[q][j] + bv, res[q + 1][j] + bv);
                    }
                }
            } else {
#pragma unroll
                for (int mi = 0; mi < MR; mi++)
                    if (mblk + m0 + mi < M_total) orow[mi] = res[mi][j] + bv;
            }
        }
    } else {
#pragma unroll
        for (int mi = 0; mi < MR; mi++) {
            int mm = mblk + m0 + mi;
            if (mm < M_total) {
                float* op = out + ((size_t)b * M_total + mm) * out_ld + nblk + n0;
                *(float4*)op = make_float4(res[mi][0], res[mi][1], res[mi][2], res[mi][3]);
                *(float4*)(op + 4) =
                    make_float4(res[mi][4], res[mi][5], res[mi][6], res[mi][7]);
            }
        }
    }
}

// ---------------- final output assembly ----------------
__global__ void __launch_bounds__(256) final_out(
    const float* __restrict__ P, const float* __restrict__ Pc,
    const float* __restrict__ vis_b, float* __restrict__ out) {
    int i = blockIdx.x;
    int b = blockIdx.y;
    int o = threadIdx.x;

    __shared__ int lut[64];
    if (o < 64) {
        int j = o;
        int d = j - i;
        int pg = -1;
        if (d >= 1 && d <= 15) {
            pg = c_off[d - 1] + i;
        } else if (d >= 17 && d <= 31 && ((d - 17) & 1) == 0 && (i & 1) == 0) {
            pg = c_off[15 + ((d - 17) >> 1)] + (i >> 1);
        } else if (d >= 35 && d <= 63 && ((d - 35) & 3) == 0 && (i & 3) == 0) {
            pg = c_off[23 + ((d - 35) >> 2)] + (i >> 2);
        }
        lut[j] = pg;
    }
    __syncthreads();

    float vb = __ldg(vis_b + o);
    float p1 = P[((size_t)b * NG + i) * 768 + o];
    float p2x = P[((size_t)b * NG + i) * 768 + 256 + o];
    const float* P3b = P + (size_t)b * NG * 768 + 512 + o;
    const float* Pcb = Pc + (size_t)b * PPAD * 256 + o;

    float accr[64];
#pragma unroll
    for (int j = 0; j < 64; j++) {
        float v = vb;
        if (j == i) {
            v += p1 + p2x + P3b[(size_t)j * 768];
        } else {
            int pg = lut[j];
            if (pg >= 0) v += p1 + Pcb[(size_t)pg * 256] + P3b[(size_t)j * 768];
        }
        accr[j] = v;
    }

    float4* op = (float4*)(out + (((size_t)b * DCH + o) * NG + i) * NG);
#pragma unroll
    for (int q = 0; q < 16; q++)
        op[q] = make_float4(accr[4 * q], accr[4 * q + 1], accr[4 * q + 2], accr[4 * q + 3]);
}

// ---------------- host ----------------
static inline int smem_bytesX(int tm) {
    int wgs = 2 * 16 * tm + 2 * 16 * 64;  // floats per slice
    int total = 4 * wgs * 4;
    int red = 3 * tm * 64 * 4;
    return total > red ? total : red;
}

extern "C" void kernel_launch(void* const* d_in, const int* in_sizes, int n_in,
                              void* d_out, int out_size) {
    const float* x  = (const float*)d_in[0];
    const float* w2 = (const float*)d_in[1];
    const float* b2 = (const float*)d_in[2];
    const float* w3 = (const float*)d_in[3];
    const float* b3 = (const float*)d_in[4];
    const float* vw = (const float*)d_in[5];
    const float* vb = (const float*)d_in[6];
    float* out = (float*)d_out;

    float *wT2, *wT3, *wP, *cur, *Pc, *P;
    cudaGetSymbolAddress((void**)&wT2, g_wT2);
    cudaGetSymbolAddress((void**)&wT3, g_wT3);
    cudaGetSymbolAddress((void**)&wP, g_wP);
    cudaGetSymbolAddress((void**)&cur, g_cur);
    cudaGetSymbolAddress((void**)&Pc, g_Pc);
    cudaGetSymbolAddress((void**)&P, g_P);

    cudaFuncSetAttribute(conv_gemmX<2, 64, false>,
                         cudaFuncAttributeMaxDynamicSharedMemorySize, smem_bytesX(64));
    cudaFuncSetAttribute(conv_gemmX<2, 32, false>,
                         cudaFuncAttributeMaxDynamicSharedMemorySize, smem_bytesX(32));
    cudaFuncSetAttribute(conv_gemmX<2, 16, false>,
                         cudaFuncAttributeMaxDynamicSharedMemorySize, smem_bytesX(16));
    cudaFuncSetAttribute(conv_gemmX<3, 32, false>,
                         cudaFuncAttributeMaxDynamicSharedMemorySize, smem_bytesX(32));
    cudaFuncSetAttribute(conv_gemmX<3, 16, false>,
                         cudaFuncAttributeMaxDynamicSharedMemorySize, smem_bytesX(16));
    cudaFuncSetAttribute(conv_gemmX<1, 64, true>,
                         cudaFuncAttributeMaxDynamicSharedMemorySize, smem_bytesX(64));

    dim3 tb(32, 8);
    trans_k<<<dim3(512 / 32, 256 / 32, 29), tb>>>(w2, wT2, 256, 512, 512, 256,
                                                  (size_t)256 * 512, (size_t)256 * 512);
    trans_k<<<dim3(768 / 32, 256 / 32, 2), tb>>>(w3, wT3, 256, 768, 768, 256,
                                                 (size_t)256 * 768, (size_t)256 * 768);
    trans_k<<<dim3(256 / 32, 256 / 32, 3), tb>>>(vw, wP, 256, 256, 768, 768,
                                                 (size_t)256, (size_t)256);

    int i2 = 0, i3 = 0;
    int Lprev = NG;
    for (int l = 0; l < 31; l++) {
        int ksz = (l == 15 || l == 23) ? 3 : 2;
        int cs = (ksz == 3) ? 2 : 1;
        int Lout = (Lprev - ksz) / cs + 1;
        const float* inp = (l == 0) ? x : cur;
        int in_row = (l == 0) ? NG : PPAD;
        int in_off = (l == 0) ? 0 : h_off[l - 1];
        dim3 grid(1, 4, BATCH);
        if (ksz == 2) {
            const float* wt = wT2 + (size_t)i2 * 512 * 256;
            const float* bi = b2 + (size_t)i2 * 256;
            i2++;
            if (Lout > 32)
                conv_gemmX<2, 64, false><<<grid, 256, smem_bytesX(64)>>>(
                    inp, in_row, in_off, cs, wt, 256, bi, cur, PPAD, h_off[l], Lout);
            else if (Lout > 16)
                conv_gemmX<2, 32, false><<<grid, 256, smem_bytesX(32)>>>(
                    inp, in_row, in_off, cs, wt, 256, bi, cur, PPAD, h_off[l], Lout);
            else
                conv_gemmX<2, 16, false><<<grid, 256, smem_bytesX(16)>>>(
                    inp, in_row, in_off, cs, wt, 256, bi, cur, PPAD, h_off[l], Lout);
        } else {
            const float* wt = wT3 + (size_t)i3 * 768 * 256;
            const float* bi = b3 + (size_t)i3 * 256;
            i3++;
            if (Lout > 16)
                conv_gemmX<3, 32, false><<<grid, 256, smem_bytesX(32)>>>(
                    inp, in_row, in_off, cs, wt, 256, bi, cur, PPAD, h_off[l], Lout);
            else
                conv_gemmX<3, 16, false><<<grid, 256, smem_bytesX(16)>>>(
                    inp, in_row, in_off, cs, wt, 256, bi, cur, PPAD, h_off[l], Lout);
        }
        Lprev = Lout;
    }

    // merged x projections: [B][64][768]
    conv_gemmX<1, 64, true><<<dim3(1, 12, BATCH), 256, smem_bytesX(64)>>>(
        x, NG, 0, 1, wP, 768, nullptr, P, 768, 0, NG);
    // Pc: [B][1088][256]
    conv_gemmX<1, 64, true><<<dim3(17, 4, BATCH), 256, smem_bytesX(64)>>>(
        cur, PPAD, 0, 1, wP + 256, 768, nullptr, Pc, 256, 0, PPAD);

    final_out<<<dim3(NG, BATCH), 256>>>(P, Pc, vb, out);
}

// round 6
// speedup vs baseline: 1.5251x; 1.1421x over previous
#include <cuda_runtime.h>
#include <cstddef>

#define BATCH 32
#define DCH 256
#define NG 64
#define PPAD 1088   // padded total conv positions (17 * 64)

__constant__ int c_off[31] = {0,64,128,192,252,312,372,432,488,544,600,656,708,760,812,
                              864,888,912,936,960,980,1000,1020,
                              1040,1048,1056,1064,1072,1076,1080,1084};

// ---------------- scratch ----------------
__device__ float g_wT2[29 * 512 * 256];
__device__ float g_wT3[2 * 768 * 256];
__device__ float g_wP[256 * 768];
__device__ float g_cur[(size_t)BATCH * DCH * PPAD];
__device__ float g_Pc[(size_t)BATCH * PPAD * DCH];
__device__ float g_P[(size_t)BATCH * NG * 768];

// ---------------- f32x2 helpers ----------------
__device__ __forceinline__ void fma2(unsigned long long& d, unsigned long long a,
                                     unsigned long long b) {
    asm("fma.rn.f32x2 %0, %1, %2, %3;" : "=l"(d) : "l"(a), "l"(b), "l"(d));
}
__device__ __forceinline__ unsigned long long dup2(float x) {
    unsigned long long r;
    unsigned int xi = __float_as_uint(x);
    asm("mov.b64 %0, {%1, %1};" : "=l"(r) : "r"(xi));
    return r;
}
__device__ __forceinline__ void cluster_sync_all() {
    asm volatile("barrier.cluster.arrive.aligned;" ::: "memory");
    asm volatile("barrier.cluster.wait.aligned;" ::: "memory");
}

// ---------------- generalized transpose ----------------
__global__ void trans_k(const float* __restrict__ in, float* __restrict__ out,
                        int R, int C, int in_ld, int out_ld,
                        size_t in_bs, size_t out_bs) {
    __shared__ float tile[32][33];
    int bat = blockIdx.z;
    int c0 = blockIdx.x * 32, r0 = blockIdx.y * 32;
    const float* ib = in + (size_t)bat * in_bs;
    float* ob = out + (size_t)bat * out_bs;
    int tx = threadIdx.x, ty = threadIdx.y;
#pragma unroll
    for (int s = 0; s < 32; s += 8) {
        int r = r0 + ty + s, c = c0 + tx;
        if (r < R && c < C) tile[ty + s][tx] = ib[(size_t)r * in_ld + c];
    }
    __syncthreads();
#pragma unroll
    for (int s = 0; s < 32; s += 8) {
        int c = c0 + ty + s, r = r0 + tx;
        if (c < C && r < R) ob[(size_t)c * out_ld + r] = tile[tx][ty + s];
    }
}

// ---------------- per-layer GEMM body (R3 internals, device function) ----------------
// out[b, n, out_off + m] = bias[n] + sum_{c,kk} in[b, c, in_off+m*cs+kk]*wT[(c*KSZ+kk)*256+n]
// 256 threads = 2 warpgroups split K; 4x8 per-thread fragment; TM x 64 tile at mblk=0.
template <int KSZ, int TM>
__device__ __forceinline__ void gemm_layer(
    const float* __restrict__ in, int in_row_len, int in_off, int cstride,
    const float* __restrict__ wT, const float* __restrict__ bias,
    float* __restrict__ outp, int out_off, int M_total,
    int b, int nblk, float* smem) {
    constexpr int KTOT = KSZ * 256;
    constexpr int KH = KTOT / 2;
    constexpr int KC = (KSZ == 3) ? 24 : 32;
    constexpr int NCH = KH / KC;
    constexpr int AG = 128 / TM;
    constexpr int NA = KC / AG;
    constexpr int NB = KC / 8;
    constexpr int MR = TM / 16;
    constexpr int WGS = 2 * KC * TM + 2 * KC * 64;

    int tid = threadIdx.x;
    int wg = tid >> 7;
    int wtid = tid & 127;
    float* As = smem + wg * WGS;
    float* Bs = As + 2 * KC * TM;
    float* Red = smem + 2 * WGS;  // [TM][64]

    int m0 = (wtid & 15) * MR;
    int n0 = (wtid >> 4) * 8;
    int am = wtid % TM;
    int ak0 = wtid / TM;
    int bkb = wtid >> 4;
    int bn = (wtid & 15) * 4;

    const float* inb = in + (size_t)b * DCH * in_row_len + in_off;
    int kbase = wg * KH;

    float aA[NA];
    float4 bB[NB];
    auto gload = [&](int ch) {
        int c0k = kbase + ch * KC;
#pragma unroll
        for (int i = 0; i < NA; i++) {
            int k = c0k + ak0 + AG * i;
            int c = k / KSZ;
            int kk = k - c * KSZ;
            aA[i] = (am < M_total)
                        ? inb[(size_t)c * in_row_len + am * cstride + kk]
                        : 0.f;
        }
#pragma unroll
        for (int i = 0; i < NB; i++) {
            int k = c0k + bkb + 8 * i;
            bB[i] = *(const float4*)&wT[(size_t)k * 256 + nblk + bn];
        }
    };
    auto sts = [&](int buf) {
#pragma unroll
        for (int i = 0; i < NA; i++)
            As[buf * KC * TM + (ak0 + AG * i) * TM + am] = aA[i];
#pragma unroll
        for (int i = 0; i < NB; i++)
            *(float4*)&Bs[buf * KC * 64 + (bkb + 8 * i) * 64 + bn] = bB[i];
    };

    unsigned long long acc[MR][4];
#pragma unroll
    for (int mi = 0; mi < MR; mi++)
#pragma unroll
        for (int p = 0; p < 4; p++) acc[mi][p] = 0ULL;

    gload(0);
    sts(0);
    __syncthreads();

#pragma unroll 1
    for (int ch = 0; ch < NCH; ch++) {
        int buf = ch & 1;
        if (ch + 1 < NCH) gload(ch + 1);
#pragma unroll
        for (int k = 0; k < KC; k++) {
            float a[MR];
            const float* ap = &As[buf * KC * TM + k * TM + m0];
            if (MR == 4) {
                float4 v = *(const float4*)ap;
                a[0] = v.x; a[1] = v.y; a[2] = v.z; a[3] = v.w;
            } else if (MR == 2) {
                float2 v = *(const float2*)ap;
                a[0] = v.x; a[1] = v.y;
            } else {
                a[0] = *ap;
            }
            const float* bp = &Bs[buf * KC * 64 + k * 64 + n0];
            ulonglong2 bl = *(const ulonglong2*)bp;
            ulonglong2 bh = *(const ulonglong2*)(bp + 4);
#pragma unroll
            for (int mi = 0; mi < MR; mi++) {
                unsigned long long ad = dup2(a[mi]);
                fma2(acc[mi][0], ad, bl.x);
                fma2(acc[mi][1], ad, bl.y);
                fma2(acc[mi][2], ad, bh.x);
                fma2(acc[mi][3], ad, bh.y);
            }
        }
        if (ch + 1 < NCH) {
            sts(buf ^ 1);
            __syncthreads();
        }
    }

    float res[MR][8];
#pragma unroll
    for (int mi = 0; mi < MR; mi++)
#pragma unroll
        for (int p = 0; p < 4; p++) {
            union { unsigned long long u; float2 f; } cv;
            cv.u = acc[mi][p];
            res[mi][2 * p] = cv.f.x;
            res[mi][2 * p + 1] = cv.f.y;
        }

    __syncthreads();
    if (wg == 1) {
#pragma unroll
        for (int mi = 0; mi < MR; mi++) {
            float* rp = &Red[(m0 + mi) * 64 + n0];
            *(float4*)rp = make_float4(res[mi][0], res[mi][1], res[mi][2], res[mi][3]);
            *(float4*)(rp + 4) =
                make_float4(res[mi][4], res[mi][5], res[mi][6], res[mi][7]);
        }
    }
    __syncthreads();

    if (wg == 0) {
#pragma unroll
        for (int mi = 0; mi < MR; mi++) {
            const float* rp = &Red[(m0 + mi) * 64 + n0];
#pragma unroll
            for (int j = 0; j < 8; j++) res[mi][j] += rp[j];
        }
#pragma unroll
        for (int j = 0; j < 8; j++) {
            int n = nblk + n0 + j;
            float bv = __ldg(bias + n);
            float* orow = outp + ((size_t)b * DCH + n) * PPAD + out_off + m0;
#pragma unroll
            for (int mi = 0; mi < MR; mi++)
                if (m0 + mi < M_total) orow[mi] = res[mi][j] + bv;
        }
    }
    __syncthreads();  // smem safe to reuse next layer (Red read done)
}

// ---------------- fused 31-layer chain: persistent, 4-CTA clusters ----------------
__global__ void __launch_bounds__(256, 1) __cluster_dims__(4, 1, 1)
chain_fused(const float* __restrict__ x,
            const float* __restrict__ wT2, const float* __restrict__ b2,
            const float* __restrict__ wT3, const float* __restrict__ b3,
            float* __restrict__ cur) {
    extern __shared__ float smem[];
    int b = blockIdx.x >> 2;
    int nblk = (blockIdx.x & 3) * 64;

    // layers 0..14: ksz2, TM=64, Lout = 63-l
    int i2 = 0;
#pragma unroll 1
    for (int l = 0; l < 15; l++) {
        const float* in = (l == 0) ? x : cur;
        int irl = (l == 0) ? NG : PPAD;
        int ioff = (l == 0) ? 0 : c_off[l - 1];
        gemm_layer<2, 64>(in, irl, ioff, 1, wT2 + (size_t)i2 * 512 * 256,
                          b2 + i2 * 256, cur, c_off[l], 63 - l, b, nblk, smem);
        i2++;
        cluster_sync_all();
    }
    // layer 15: ksz3, TM=32, Lout=24
    gemm_layer<3, 32>(cur, PPAD, c_off[14], 2, wT3, b3, cur, c_off[15], 24, b, nblk,
                      smem);
    cluster_sync_all();
    // layers 16..22: ksz2, TM=32, Lout = 39-l
#pragma unroll 1
    for (int l = 16; l < 23; l++) {
        gemm_layer<2, 32>(cur, PPAD, c_off[l - 1], 1, wT2 + (size_t)i2 * 512 * 256,
                          b2 + i2 * 256, cur, c_off[l], 39 - l, b, nblk, smem);
        i2++;
        cluster_sync_all();
    }
    // layer 23: ksz3, TM=16, Lout=8
    gemm_layer<3, 16>(cur, PPAD, c_off[22], 2, wT3 + (size_t)768 * 256, b3 + 256, cur,
                      c_off[23], 8, b, nblk, smem);
    cluster_sync_all();
    // layers 24..30: ksz2, TM=16, Lout = 31-l
#pragma unroll 1
    for (int l = 24; l < 31; l++) {
        gemm_layer<2, 16>(cur, PPAD, c_off[l - 1], 1, wT2 + (size_t)i2 * 512 * 256,
                          b2 + i2 * 256, cur, c_off[l], 31 - l, b, nblk, smem);
        i2++;
        if (l < 30) cluster_sync_all();
    }
}

// ---------------- standalone GEMM (x-proj and Pc), R3 proven version ----------------
// out[b, m, n] = sum_c in[b, c, m] * wT[c*wld + n]   (K=1 conv, transposed store)
__global__ void __launch_bounds__(256) proj_gemm(
    const float* __restrict__ in, int in_row_len,
    const float* __restrict__ wT, int wld,
    float* __restrict__ out, int out_ld, int M_total) {
    constexpr int KC = 32;
    constexpr int NCH = 4;  // KH=128 per wg
    constexpr int WGS = 2 * KC * 64 + 2 * KC * 64;

    extern __shared__ float smem[];
    int tid = threadIdx.x;
    int wg = tid >> 7;
    int wtid = tid & 127;
    float* As = smem + wg * WGS;
    float* Bs = As + 2 * KC * 64;
    float* Red = smem + 2 * WGS;

    int b = blockIdx.z;
    int nblk = blockIdx.y * 64;
    int mblk = blockIdx.x * 64;
    int m0 = (wtid & 15) * 4;
    int n0 = (wtid >> 4) * 8;
    int am = wtid & 63;
    int ak0 = wtid >> 6;
    int bkb = wtid >> 4;
    int bn = (wtid & 15) * 4;

    const float* inb = in + (size_t)b * DCH * in_row_len;
    int kbase = wg * 128;

    float aA[16];
    float4 bB[4];
    auto gload = [&](int ch) {
        int c0k = kbase + ch * KC;
#pragma unroll
        for (int i = 0; i < 16; i++) {
            int k = c0k + ak0 + 2 * i;
            int mm = mblk + am;
            aA[i] = (mm < M_total) ? inb[(size_t)k * in_row_len + mm] : 0.f;
        }
#pragma unroll
        for (int i = 0; i < 4; i++) {
            int k = c0k + bkb + 8 * i;
            bB[i] = *(const float4*)&wT[(size_t)k * wld + nblk + bn];
        }
    };
    auto sts = [&](int buf) {
#pragma unroll
        for (int i = 0; i < 16; i++)
            As[buf * KC * 64 + (ak0 + 2 * i) * 64 + am] = aA[i];
#pragma unroll
        for (int i = 0; i < 4; i++)
            *(float4*)&Bs[buf * KC * 64 + (bkb + 8 * i) * 64 + bn] = bB[i];
    };

    unsigned long long acc[4][4];
#pragma unroll
    for (int mi = 0; mi < 4; mi++)
#pragma unroll
        for (int p = 0; p < 4; p++) acc[mi][p] = 0ULL;

    gload(0);
    sts(0);
    __syncthreads();

#pragma unroll 1
    for (int ch = 0; ch < NCH; ch++) {
        int buf = ch & 1;
        if (ch + 1 < NCH) gload(ch + 1);
#pragma unroll
        for (int k = 0; k < KC; k++) {
            float4 av = *(const float4*)&As[buf * KC * 64 + k * 64 + m0];
            const float* bp = &Bs[buf * KC * 64 + k * 64 + n0];
            ulonglong2 bl = *(const ulonglong2*)bp;
            ulonglong2 bh = *(const ulonglong2*)(bp + 4);
            float a[4] = {av.x, av.y, av.z, av.w};
#pragma unroll
            for (int mi = 0; mi < 4; mi++) {
                unsigned long long ad = dup2(a[mi]);
                fma2(acc[mi][0], ad, bl.x);
                fma2(acc[mi][1], ad, bl.y);
                fma2(acc[mi][2], ad, bh.x);
                fma2(acc[mi][3], ad, bh.y);
            }
        }
        if (ch + 1 < NCH) {
            sts(buf ^ 1);
            __syncthreads();
        }
    }

    float res[4][8];
#pragma unroll
    for (int mi = 0; mi < 4; mi++)
#pragma unroll
        for (int p = 0; p < 4; p++) {
            union { unsigned long long u; float2 f; } cv;
            cv.u = acc[mi][p];
            res[mi][2 * p] = cv.f.x;
            res[mi][2 * p + 1] = cv.f.y;
        }

    __syncthreads();
    if (wg == 1) {
#pragma unroll
        for (int mi = 0; mi < 4; mi++) {
            float* rp = &Red[(m0 + mi) * 64 + n0];
            *(float4*)rp = make_float4(res[mi][0], res[mi][1], res[mi][2], res[mi][3]);
            *(float4*)(rp + 4) =
                make_float4(res[mi][4], res[mi][5], res[mi][6], res[mi][7]);
        }
    }
    __syncthreads();
    if (wg != 0) return;

#pragma unroll
    for (int mi = 0; mi < 4; mi++) {
        const float* rp = &Red[(m0 + mi) * 64 + n0];
#pragma unroll
        for (int j = 0; j < 8; j++) res[mi][j] += rp[j];
    }

#pragma unroll
    for (int mi = 0; mi < 4; mi++) {
        int mm = mblk + m0 + mi;
        if (mm < M_total) {
            float* op = out + ((size_t)b * M_total + mm) * out_ld + nblk + n0;
            *(float4*)op = make_float4(res[mi][0], res[mi][1], res[mi][2], res[mi][3]);
            *(float4*)(op + 4) =
                make_float4(res[mi][4], res[mi][5], res[mi][6], res[mi][7]);
        }
    }
}

// ---------------- final output assembly ----------------
__global__ void __launch_bounds__(256) final_out(
    const float* __restrict__ P, const float* __restrict__ Pc,
    const float* __restrict__ vis_b, float* __restrict__ out) {
    int i = blockIdx.x;
    int b = blockIdx.y;
    int o = threadIdx.x;

    __shared__ int lut[64];
    if (o < 64) {
        int j = o;
        int d = j - i;
        int pg = -1;
        if (d >= 1 && d <= 15) {
            pg = c_off[d - 1] + i;
        } else if (d >= 17 && d <= 31 && ((d - 17) & 1) == 0 && (i & 1) == 0) {
            pg = c_off[15 + ((d - 17) >> 1)] + (i >> 1);
        } else if (d >= 35 && d <= 63 && ((d - 35) & 3) == 0 && (i & 3) == 0) {
            pg = c_off[23 + ((d - 35) >> 2)] + (i >> 2);
        }
        lut[j] = pg;
    }
    __syncthreads();

    float vb = __ldg(vis_b + o);
    float p1 = P[((size_t)b * NG + i) * 768 + o];
    float p2x = P[((size_t)b * NG + i) * 768 + 256 + o];
    const float* P3b = P + (size_t)b * NG * 768 + 512 + o;
    const float* Pcb = Pc + (size_t)b * PPAD * 256 + o;

    float accr[64];
#pragma unroll
    for (int j = 0; j < 64; j++) {
        float v = vb;
        if (j == i) {
            v += p1 + p2x + P3b[(size_t)j * 768];
        } else {
            int pg = lut[j];
            if (pg >= 0) v += p1 + Pcb[(size_t)pg * 256] + P3b[(size_t)j * 768];
        }
        accr[j] = v;
    }

    float4* op = (float4*)(out + (((size_t)b * DCH + o) * NG + i) * NG);
#pragma unroll
    for (int q = 0; q < 16; q++)
        op[q] = make_float4(accr[4 * q], accr[4 * q + 1], accr[4 * q + 2], accr[4 * q + 3]);
}

// ---------------- host ----------------
#define SMEM_FUSED ((2 * (2 * 32 * 64 + 2 * 32 * 64) + 64 * 64) * 4)  // 80 KB

extern "C" void kernel_launch(void* const* d_in, const int* in_sizes, int n_in,
                              void* d_out, int out_size) {
    const float* x  = (const float*)d_in[0];
    const float* w2 = (const float*)d_in[1];
    const float* b2 = (const float*)d_in[2];
    const float* w3 = (const float*)d_in[3];
    const float* b3 = (const float*)d_in[4];
    const float* vw = (const float*)d_in[5];
    const float* vb = (const float*)d_in[6];
    float* out = (float*)d_out;

    float *wT2, *wT3, *wP, *cur, *Pc, *P;
    cudaGetSymbolAddress((void**)&wT2, g_wT2);
    cudaGetSymbolAddress((void**)&wT3, g_wT3);
    cudaGetSymbolAddress((void**)&wP, g_wP);
    cudaGetSymbolAddress((void**)&cur, g_cur);
    cudaGetSymbolAddress((void**)&Pc, g_Pc);
    cudaGetSymbolAddress((void**)&P, g_P);

    cudaFuncSetAttribute(chain_fused, cudaFuncAttributeMaxDynamicSharedMemorySize,
                         SMEM_FUSED);
    cudaFuncSetAttribute(proj_gemm, cudaFuncAttributeMaxDynamicSharedMemorySize,
                         SMEM_FUSED);

    dim3 tb(32, 8);
    trans_k<<<dim3(512 / 32, 256 / 32, 29), tb>>>(w2, wT2, 256, 512, 512, 256,
                                                  (size_t)256 * 512, (size_t)256 * 512);
    trans_k<<<dim3(768 / 32, 256 / 32, 2), tb>>>(w3, wT3, 256, 768, 768, 256,
                                                 (size_t)256 * 768, (size_t)256 * 768);
    trans_k<<<dim3(256 / 32, 256 / 32, 3), tb>>>(vw, wP, 256, 256, 768, 768,
                                                 (size_t)256, (size_t)256);

    // fused 31-layer chain: one persistent launch, 32 clusters x 4 CTAs
    chain_fused<<<128, 256, SMEM_FUSED>>>(x, wT2, b2, wT3, b3, cur);

    // merged x projections: [B][64][768]
    proj_gemm<<<dim3(1, 12, BATCH), 256, SMEM_FUSED>>>(x, NG, wP, 768, P, 768, NG);
    // Pc: [B][1088][256]
    proj_gemm<<<dim3(17, 4, BATCH), 256, SMEM_FUSED>>>(cur, PPAD, wP + 256, 768, Pc,
                                                       256, PPAD);

    final_out<<<dim3(NG, BATCH), 256>>>(P, Pc, vb, out);
}